// round 15
// baseline (speedup 1.0000x reference)
#include <cuda_runtime.h>
#include <cuda_fp16.h>
#include <mma.h>
#include <cstdint>
#include <math.h>

using namespace nvcuda;
using u32 = unsigned int;
using u64 = unsigned long long;

// ---------------- problem constants ----------------
#define Bc     4
#define Mc     50000
#define FINc   128
#define FOUTc  128
#define Kc     4
#define Ecap   800000
#define Dc     512
#define TOTROWS (Bc*Mc)
#define NSCANB 196            // ceil(Mc/256)

// ---------------- device scratch ----------------
__device__ float g_X[Kc][Mc * Dc];          // Chebyshev stack [m][b][f]; slot 0 unused
__device__ __half g_Wh[512 * 128];          // W hi  [k][n], fp16
__device__ __half g_Wl[512 * 128];          // W lo  [k][n], fp16 residual
__device__ int   g_rowptr[Mc + 1];
__device__ int   g_cursor[Mc];
__device__ u64   g_scanstate[256];
__device__ int   g_col[Ecap];
__device__ float g_val[Ecap];
__device__ float g_ssum[Bc * FOUTc];
__device__ float g_u[Bc * FOUTc];

// ---------------- cp.async helpers ----------------
__device__ __forceinline__ u32 smem_u32p(const void* p) {
    u32 a;
    asm("{ .reg .u64 t; cvta.to.shared.u64 t, %1; cvt.u32.u64 %0, t; }" : "=r"(a) : "l"(p));
    return a;
}
#define CPA16(dst, src) asm volatile("cp.async.cg.shared.global [%0], [%1], 16;" :: "r"(dst), "l"(src))
#define CPCOMMIT()      asm volatile("cp.async.commit_group;" ::: "memory")
#define CPWAIT1()       asm volatile("cp.async.wait_group 1;" ::: "memory")
#define CPWAIT0()       asm volatile("cp.async.wait_group 0;" ::: "memory")

// ---------------- 1. CSR build (+ fused weight split) ----------------
__global__ void k_count(const int* __restrict__ rows, int E,
                        const float* __restrict__ kern) {
    int gid = blockIdx.x * blockDim.x + threadIdx.x;
    int stride = gridDim.x * blockDim.x;
    if (gid < 256) g_scanstate[gid] = 0ULL;
    for (int i = gid; i < 512 * 128; i += stride) {
        int k = i >> 7, n = i & 127;
        int kc = k >> 7, f = k & 127;
        float v = kern[(f * 4 + kc) * 128 + n];
        __half h = __float2half_rn(v);
        __half l = __float2half_rn(v - __half2float(h));
        g_Wh[i] = h;
        g_Wl[i] = l;
    }
    for (int e = gid; e < E; e += stride)
        atomicAdd(&g_cursor[rows[e]], 1);
}

// single-kernel decoupled-lookback scan
__global__ void k_scan_dl() {
    __shared__ int s[256];
    __shared__ int s_prefix;
    const int b = blockIdx.x, t = threadIdx.x;
    const int i = b * 256 + t;
    int v = (i < Mc) ? g_cursor[i] : 0;
    s[t] = v;
    __syncthreads();
    #pragma unroll
    for (int off = 1; off < 256; off <<= 1) {
        int a = (t >= off) ? s[t - off] : 0;
        __syncthreads();
        s[t] += a;
        __syncthreads();
    }
    const int incl = s[t];
    const int agg  = s[255];

    if (t == 0) {
        u64 st = (b == 0) ? ((2ULL << 32) | (u32)agg) : ((1ULL << 32) | (u32)agg);
        atomicExch(&g_scanstate[b], st);
        if (b == 0) s_prefix = 0;
    }

    if (b > 0 && t < 32) {
        int running = 0;
        int idx = b - 1;
        while (true) {
            int j = idx - t;
            u64 st = 0;
            if (j >= 0) {
                do { st = atomicAdd(&g_scanstate[j], 0ULL); } while ((st >> 32) == 0);
            }
            int flag = (j >= 0) ? (int)(st >> 32) : 0;
            int val  = (int)(st & 0xffffffffULL);
            u32 pmask = __ballot_sync(0xffffffffu, flag == 2);
            if (pmask) {
                int lead = __ffs(pmask) - 1;
                int contrib = (t <= lead) ? val : 0;
                #pragma unroll
                for (int o = 16; o; o >>= 1) contrib += __shfl_down_sync(0xffffffffu, contrib, o);
                if (t == 0) s_prefix = running + contrib;
                break;
            } else {
                int contrib = (j >= 0) ? val : 0;
                #pragma unroll
                for (int o = 16; o; o >>= 1) contrib += __shfl_down_sync(0xffffffffu, contrib, o);
                running += __shfl_sync(0xffffffffu, contrib, 0);
                idx -= 32;
            }
        }
        if (t == 0)
            atomicExch(&g_scanstate[b], (2ULL << 32) | (u32)(s_prefix + agg));
    }
    __syncthreads();
    const int pre  = s_prefix;
    const int excl = incl - v + pre;
    if (i < Mc) { g_rowptr[i] = excl; g_cursor[i] = excl; }
    if (b == NSCANB - 1 && t == 255) g_rowptr[Mc] = pre + agg;
}

__global__ void k_scatter(const int* __restrict__ rows,
                          const int* __restrict__ cols,
                          const float* __restrict__ vals, int E) {
    for (int e = blockIdx.x * blockDim.x + threadIdx.x; e < E;
         e += gridDim.x * blockDim.x) {
        int r    = rows[e];
        int slot = atomicAdd(&g_cursor[r], 1);
        g_col[slot] = cols[e];
        g_val[slot] = vals[e];
    }
}

// ---------------- 2. SpMM (templated) ----------------
template<int LIN, int LPREV, int BETA>
__global__ void k_spmm_t(const float* __restrict__ Xin,
                         const float* __restrict__ Xprev,
                         float* __restrict__ Xout, float alpha, float beta) {
    const int r  = blockIdx.x;
    const u32 t  = threadIdx.x;
    const u32 bo = (t >> 5) * (u32)Mc * 32u + (t & 31);
    const int p0 = g_rowptr[r];
    const int p1 = g_rowptr[r + 1];
    const float4* __restrict__ Xi = reinterpret_cast<const float4*>(Xin);

    float4 acc = make_float4(0.f, 0.f, 0.f, 0.f);
    int p = p0;
    for (; p + 7 < p1; p += 8) {
        float4 xv[8];
        float  vv[8];
        #pragma unroll
        for (int j = 0; j < 8; ++j) {
            u32 c = (u32)g_col[p + j];
            vv[j] = g_val[p + j];
            u32 i = LIN ? (c * 128u + t) : (c * 32u + bo);
            xv[j] = Xi[i];
        }
        #pragma unroll
        for (int j = 0; j < 8; ++j) {
            acc.x = fmaf(vv[j], xv[j].x, acc.x);
            acc.y = fmaf(vv[j], xv[j].y, acc.y);
            acc.z = fmaf(vv[j], xv[j].z, acc.z);
            acc.w = fmaf(vv[j], xv[j].w, acc.w);
        }
    }
    if (p + 3 < p1) {
        float4 xv[4];
        float  vv[4];
        #pragma unroll
        for (int j = 0; j < 4; ++j) {
            u32 c = (u32)g_col[p + j];
            vv[j] = g_val[p + j];
            u32 i = LIN ? (c * 128u + t) : (c * 32u + bo);
            xv[j] = Xi[i];
        }
        #pragma unroll
        for (int j = 0; j < 4; ++j) {
            acc.x = fmaf(vv[j], xv[j].x, acc.x);
            acc.y = fmaf(vv[j], xv[j].y, acc.y);
            acc.z = fmaf(vv[j], xv[j].z, acc.z);
            acc.w = fmaf(vv[j], xv[j].w, acc.w);
        }
        p += 4;
    }
    for (; p < p1; ++p) {
        u32 c = (u32)g_col[p];
        float v0 = g_val[p];
        u32 i = LIN ? (c * 128u + t) : (c * 32u + bo);
        float4 xa = Xi[i];
        acc.x = fmaf(v0, xa.x, acc.x);
        acc.y = fmaf(v0, xa.y, acc.y);
        acc.z = fmaf(v0, xa.z, acc.z);
        acc.w = fmaf(v0, xa.w, acc.w);
    }

    float4 o;
    if (BETA) {
        u32 ip = LPREV ? ((u32)r * 128u + t) : ((u32)r * 32u + bo);
        float4 pv = reinterpret_cast<const float4*>(Xprev)[ip];
        o.x = fmaf(alpha, acc.x, beta * pv.x);
        o.y = fmaf(alpha, acc.y, beta * pv.y);
        o.z = fmaf(alpha, acc.z, beta * pv.z);
        o.w = fmaf(alpha, acc.w, beta * pv.w);
    } else {
        o.x = alpha * acc.x; o.y = alpha * acc.y;
        o.z = alpha * acc.z; o.w = alpha * acc.w;
    }
    reinterpret_cast<float4*>(Xout)[(u32)r * 128u + t] = o;
}

// ---------------- 3. wmma fp16 GEMM, cp.async double-buffered ----------------
// CTA tile 128(M) x 128(N); K=512 in 16 stages of 32.
// A single fp16 (quant err ~2.8e-4 RMS), B = fp16 hi + lo (2-term).
// D = A*B1 + A*B2, fp32 accumulate. 2 MMAs/k-step (was 3 with bf16 3-term).
#define RAWLD 36      // raw A row stride (floats): 144 B
#define ALD 40        // converted A ldm (halves)
#define BLD 136       // B ldm (halves): 272 B rows
// dynamic smem layout (bytes)
#define OFF_RAWA 0                         // [2][128][RAWLD] f32 : 2*18432
#define OFF_B    36864                     // [2][Bh 32x136 | Bl 32x136] : 2*17408
#define OFF_AH   (36864 + 34816)           // [128][ALD] fp16 : 10240
#define GSMEM    (OFF_AH + 10240)          // 81920 B

__global__ __launch_bounds__(256)
void k_gemm_wmma(const float* __restrict__ x, float* __restrict__ Y) {
    extern __shared__ char dsm[];
    float* rawA = reinterpret_cast<float*>(dsm + OFF_RAWA);
    __half* Ah = reinterpret_cast<__half*>(dsm + OFF_AH);
    __shared__ int2  rowB[128];
    __shared__ float stg[8][16][16];

    const int t   = threadIdx.x;
    const int wid = t >> 5, lid = t & 31;
    const int wm  = wid & 3;
    const int wn  = wid >> 2;
    const int r0  = blockIdx.x * 128;
    const bool full = (r0 + 128 <= TOTROWS);
    const u32 sbase = smem_u32p(dsm);

    if (t < 128) {
        int gr = r0 + t;
        int2 rb = make_int2(-1, -1);
        if (gr < TOTROWS) {
            int b = gr / Mc; int m = gr - b * Mc;
            rb.x = (b * Mc + m) * 128;   // x native [b][m][f]
            rb.y = m * 512 + b * 128;    // g_X [m][b][f]
        }
        rowB[t] = rb;
    }
    __syncthreads();

    wmma::fragment<wmma::accumulator, 16, 16, 16, float> acc[2][4];
    #pragma unroll
    for (int mi = 0; mi < 2; ++mi)
        #pragma unroll
        for (int ni = 0; ni < 4; ++ni)
            wmma::fill_fragment(acc[mi][ni], 0.0f);

    // issue cp.async for stage c into buffer c&1
    auto issue = [&](int c) {
        const int buf = c & 1;
        const int kcheb = c >> 2;
        const int f0 = (c & 3) << 5;
        const float* Asrc = (kcheb == 0) ? x : g_X[kcheb];
        const u32 adst0 = sbase + OFF_RAWA + buf * 18432;
        #pragma unroll
        for (int q = 0; q < 4; ++q) {
            int idx = t + (q << 8);
            int row = idx >> 3, seg = idx & 7;
            int2 rb = rowB[row];
            int base = (kcheb == 0) ? rb.x : rb.y;
            if (rb.x < 0) base = 0;   // tail rows: valid dummy src, result discarded
            const float* src = Asrc + base + f0 + (seg << 2);
            CPA16(adst0 + row * 144 + (seg << 4), src);
        }
        const u32 bdst0 = sbase + OFF_B + buf * 17408;
        #pragma unroll
        for (int q = 0; q < 4; ++q) {
            int idx = t + (q << 8);
            int arr = idx >> 9;          // 0 = hi, 1 = lo
            int rix = (idx >> 4) & 31;
            int seg = idx & 15;
            const __half* src =
                (arr ? g_Wl : g_Wh) + ((c << 5) + rix) * 128 + (seg << 3);
            CPA16(bdst0 + arr * 8704 + rix * 272 + (seg << 4), src);
        }
    };

    issue(0);
    CPCOMMIT();

    for (int c = 0; c < 16; ++c) {
        const int buf = c & 1;
        if (c < 15) { issue(c + 1); CPCOMMIT(); CPWAIT1(); }
        else        { CPWAIT0(); }
        __syncthreads();

        // convert rawA[buf] (128x32 f32) -> Ah (fp16)
        const float* ra = rawA + buf * 4608;
        #pragma unroll
        for (int q = 0; q < 4; ++q) {
            int idx = t + (q << 8);
            int row = idx >> 3, c0 = (idx & 7) << 2;
            float4 v = *reinterpret_cast<const float4*>(ra + row * RAWLD + c0);
            __half2 h01 = __floats2half2_rn(v.x, v.y);
            __half2 h23 = __floats2half2_rn(v.z, v.w);
            uint2 u;
            u.x = *reinterpret_cast<u32*>(&h01);
            u.y = *reinterpret_cast<u32*>(&h23);
            *reinterpret_cast<uint2*>(Ah + row * ALD + c0) = u;
        }
        __syncthreads();

        const __half* Bh = reinterpret_cast<const __half*>(dsm + OFF_B + buf * 17408);
        const __half* Bl = Bh + 4352;   // 8704 B / 2

        #pragma unroll
        for (int kk = 0; kk < 2; ++kk) {
            wmma::fragment<wmma::matrix_a, 16, 16, 16, __half, wmma::row_major> ah[2];
            #pragma unroll
            for (int mi = 0; mi < 2; ++mi)
                wmma::load_matrix_sync(ah[mi], Ah + (wm * 32 + mi * 16) * ALD + kk * 16, ALD);
            #pragma unroll
            for (int ni = 0; ni < 4; ++ni) {
                wmma::fragment<wmma::matrix_b, 16, 16, 16, __half, wmma::row_major> bh, bl;
                wmma::load_matrix_sync(bh, Bh + (kk * 16) * BLD + wn * 64 + ni * 16, BLD);
                wmma::load_matrix_sync(bl, Bl + (kk * 16) * BLD + wn * 64 + ni * 16, BLD);
                #pragma unroll
                for (int mi = 0; mi < 2; ++mi) {
                    wmma::mma_sync(acc[mi][ni], ah[mi], bh, acc[mi][ni]);
                    wmma::mma_sync(acc[mi][ni], ah[mi], bl, acc[mi][ni]);
                }
            }
        }
        __syncthreads();
    }

    // epilogue: ReLU + store
    #pragma unroll
    for (int mi = 0; mi < 2; ++mi)
        #pragma unroll
        for (int ni = 0; ni < 4; ++ni)
            #pragma unroll
            for (int e = 0; e < acc[mi][ni].num_elements; ++e)
                acc[mi][ni].x[e] = fmaxf(acc[mi][ni].x[e], 0.0f);

    if (full) {
        #pragma unroll
        for (int mi = 0; mi < 2; ++mi)
            #pragma unroll
            for (int ni = 0; ni < 4; ++ni) {
                int gr = r0 + wm * 32 + mi * 16;
                int gc = wn * 64 + ni * 16;
                wmma::store_matrix_sync(Y + (size_t)gr * 128 + gc,
                                        acc[mi][ni], 128, wmma::mem_row_major);
            }
    } else {
        for (int mi = 0; mi < 2; ++mi)
            for (int ni = 0; ni < 4; ++ni) {
                wmma::store_matrix_sync(&stg[wid][0][0], acc[mi][ni], 16,
                                        wmma::mem_row_major);
                __syncwarp();
                int gc = wn * 64 + ni * 16;
                #pragma unroll
                for (int e = lid; e < 256; e += 32) {
                    int rr = e >> 4, cc = e & 15;
                    int gr = r0 + wm * 32 + mi * 16 + rr;
                    if (gr < TOTROWS)
                        Y[(size_t)gr * 128 + gc + cc] = stg[wid][rr][cc];
                }
                __syncwarp();
            }
    }
}

// ---------------- 4. column sums for mean ----------------
__global__ void k_mean(const float* __restrict__ Y) {
    const int b = blockIdx.y;
    const int t = threadIdx.x;
    const int m0 = blockIdx.x * 128;
    const int m1 = min(m0 + 128, Mc);
    float acc = 0.0f;
    for (int m = m0; m < m1; ++m)
        acc += Y[((size_t)b * Mc + m) * 128 + t];
    atomicAdd(&g_ssum[b * 128 + t], acc);
}

// ---------------- 5. SE block ----------------
__global__ void k_se(const float* __restrict__ Wd, const float* __restrict__ bd,
                     const float* __restrict__ Wu, const float* __restrict__ bu) {
    __shared__ float s[Bc][128];
    __shared__ float d[Bc][16];
    const int t = threadIdx.x;
    #pragma unroll
    for (int b = 0; b < Bc; ++b)
        s[b][t] = g_ssum[b * 128 + t] * (1.0f / (float)Mc);
    __syncthreads();
    if (t < 64) {
        int b = t >> 4, j = t & 15;
        float z = bd[j];
        for (int f = 0; f < 128; ++f) z = fmaf(s[b][f], Wd[f * 16 + j], z);
        d[b][j] = z / (1.0f + expf(-z));
    }
    __syncthreads();
    #pragma unroll
    for (int b = 0; b < Bc; ++b) {
        float z = bu[t];
        for (int j = 0; j < 16; ++j) z = fmaf(d[b][j], Wu[j * 128 + t], z);
        g_u[b * 128 + t] = 1.0f / (1.0f + expf(-z));
    }
}

// ---------------- 6. gated scale ----------------
__global__ void k_scale(float* __restrict__ Y) {
    float4* Y4 = reinterpret_cast<float4*>(Y);
    const int N4 = Bc * Mc * 32;
    for (int i = blockIdx.x * blockDim.x + threadIdx.x; i < N4;
         i += gridDim.x * blockDim.x) {
        int o4 = i & 31;
        int b  = i / (Mc * 32);
        float4 u = reinterpret_cast<const float4*>(g_u)[b * 32 + o4];
        float4 v = Y4[i];
        v.x *= u.x; v.y *= u.y; v.z *= u.z; v.w *= u.w;
        Y4[i] = v;
    }
}

// ---------------- launch ----------------
extern "C" void kernel_launch(void* const* d_in, const int* in_sizes, int n_in,
                              void* d_out, int out_size) {
    const float* x      = (const float*)d_in[0];
    const float* L_vals = (const float*)d_in[1];
    const int*   L_rows = (const int*)  d_in[2];
    const int*   L_cols = (const int*)  d_in[3];
    const float* kern   = (const float*)d_in[4];
    const float* Wd     = (const float*)d_in[5];
    const float* bd     = (const float*)d_in[6];
    const float* Wu     = (const float*)d_in[7];
    const float* bu     = (const float*)d_in[8];
    float* Y = (float*)d_out;
    const int E = in_sizes[1];

    float* X1 = nullptr; cudaGetSymbolAddress((void**)&X1, g_X);
    float* Xs1 = X1 + (size_t)1 * Mc * Dc;
    float* Xs2 = X1 + (size_t)2 * Mc * Dc;
    float* Xs3 = X1 + (size_t)3 * Mc * Dc;
    int*   curp = nullptr; cudaGetSymbolAddress((void**)&curp, g_cursor);
    float* ssump = nullptr; cudaGetSymbolAddress((void**)&ssump, g_ssum);

    static int smem_set = 0;
    if (!smem_set) {
        cudaFuncSetAttribute(k_gemm_wmma,
                             cudaFuncAttributeMaxDynamicSharedMemorySize, GSMEM);
        smem_set = 1;
    }

    cudaMemsetAsync(curp, 0, Mc * sizeof(int));                       // node 0
    cudaMemsetAsync(ssump, 0, Bc * FOUTc * sizeof(float));            // node 1

    k_count  <<<(E + 255) / 256, 256>>>(L_rows, E, kern);             // 2
    k_scan_dl<<<NSCANB, 256>>>();                                     // 3
    k_scatter<<<(E + 255) / 256, 256>>>(L_rows, L_cols, L_vals, E);   // 4

    k_spmm_t<0,0,0><<<Mc, 128>>>(x,   nullptr, Xs1, 1.0f,  0.0f);     // 5 <- ncu -s 5
    k_spmm_t<1,0,1><<<Mc, 128>>>(Xs1, x,       Xs2, 2.0f, -1.0f);     // 6
    k_spmm_t<1,1,1><<<Mc, 128>>>(Xs2, Xs1,     Xs3, 2.0f, -1.0f);     // 7

    k_gemm_wmma<<<(TOTROWS + 127) / 128, 256, GSMEM>>>(x, Y);         // 8
    k_mean  <<<dim3((Mc + 127) / 128, Bc), 128>>>(Y);                 // 9
    k_se    <<<1, 128>>>(Wd, bd, Wu, bu);                             // 10
    k_scale <<<2048, 256>>>(Y);                                       // 11
}

// round 16
// speedup vs baseline: 1.2889x; 1.2889x over previous
#include <cuda_runtime.h>
#include <cuda_fp16.h>
#include <mma.h>
#include <cstdint>
#include <math.h>

using namespace nvcuda;
using u32 = unsigned int;
using u64 = unsigned long long;

// ---------------- problem constants ----------------
#define Bc     4
#define Mc     50000
#define FINc   128
#define FOUTc  128
#define Kc     4
#define Ecap   800000
#define Dc     512
#define TOTROWS (Bc*Mc)
#define NSCANB 196            // ceil(Mc/256)

// ---------------- device scratch ----------------
__device__ float g_X[Kc][Mc * Dc];          // Chebyshev stack [m][b][f]; slot 0 unused
__device__ __half g_Wh[512 * 128];          // W hi  [k][n], fp16
__device__ __half g_Wl[512 * 128];          // W lo  [k][n], fp16 residual
__device__ int   g_rowptr[Mc + 1];
__device__ int   g_cursor[Mc];
__device__ u64   g_scanstate[256];
__device__ int   g_col[Ecap];
__device__ float g_val[Ecap];
__device__ float g_ssum[Bc * FOUTc];
__device__ float g_u[Bc * FOUTc];

// ---------------- cp.async helpers ----------------
__device__ __forceinline__ u32 smem_u32p(const void* p) {
    u32 a;
    asm("{ .reg .u64 t; cvta.to.shared.u64 t, %1; cvt.u32.u64 %0, t; }" : "=r"(a) : "l"(p));
    return a;
}
#define CPA16(dst, src) asm volatile("cp.async.cg.shared.global [%0], [%1], 16;" :: "r"(dst), "l"(src))
#define CPCOMMIT()      asm volatile("cp.async.commit_group;" ::: "memory")
#define CPWAIT1()       asm volatile("cp.async.wait_group 1;" ::: "memory")
#define CPWAIT0()       asm volatile("cp.async.wait_group 0;" ::: "memory")

// ---------------- 1. CSR build (+ fused weight split) ----------------
__global__ void k_count(const int* __restrict__ rows, int E,
                        const float* __restrict__ kern) {
    int gid = blockIdx.x * blockDim.x + threadIdx.x;
    int stride = gridDim.x * blockDim.x;
    if (gid < 256) g_scanstate[gid] = 0ULL;
    for (int i = gid; i < 512 * 128; i += stride) {
        int k = i >> 7, n = i & 127;
        int kc = k >> 7, f = k & 127;
        float v = kern[(f * 4 + kc) * 128 + n];
        __half h = __float2half_rn(v);
        __half l = __float2half_rn(v - __half2float(h));
        g_Wh[i] = h;
        g_Wl[i] = l;
    }
    for (int e = gid; e < E; e += stride)
        atomicAdd(&g_cursor[rows[e]], 1);
}

// single-kernel decoupled-lookback scan
__global__ void k_scan_dl() {
    __shared__ int s[256];
    __shared__ int s_prefix;
    const int b = blockIdx.x, t = threadIdx.x;
    const int i = b * 256 + t;
    int v = (i < Mc) ? g_cursor[i] : 0;
    s[t] = v;
    __syncthreads();
    #pragma unroll
    for (int off = 1; off < 256; off <<= 1) {
        int a = (t >= off) ? s[t - off] : 0;
        __syncthreads();
        s[t] += a;
        __syncthreads();
    }
    const int incl = s[t];
    const int agg  = s[255];

    if (t == 0) {
        u64 st = (b == 0) ? ((2ULL << 32) | (u32)agg) : ((1ULL << 32) | (u32)agg);
        atomicExch(&g_scanstate[b], st);
        if (b == 0) s_prefix = 0;
    }

    if (b > 0 && t < 32) {
        int running = 0;
        int idx = b - 1;
        while (true) {
            int j = idx - t;
            u64 st = 0;
            if (j >= 0) {
                do { st = atomicAdd(&g_scanstate[j], 0ULL); } while ((st >> 32) == 0);
            }
            int flag = (j >= 0) ? (int)(st >> 32) : 0;
            int val  = (int)(st & 0xffffffffULL);
            u32 pmask = __ballot_sync(0xffffffffu, flag == 2);
            if (pmask) {
                int lead = __ffs(pmask) - 1;
                int contrib = (t <= lead) ? val : 0;
                #pragma unroll
                for (int o = 16; o; o >>= 1) contrib += __shfl_down_sync(0xffffffffu, contrib, o);
                if (t == 0) s_prefix = running + contrib;
                break;
            } else {
                int contrib = (j >= 0) ? val : 0;
                #pragma unroll
                for (int o = 16; o; o >>= 1) contrib += __shfl_down_sync(0xffffffffu, contrib, o);
                running += __shfl_sync(0xffffffffu, contrib, 0);
                idx -= 32;
            }
        }
        if (t == 0)
            atomicExch(&g_scanstate[b], (2ULL << 32) | (u32)(s_prefix + agg));
    }
    __syncthreads();
    const int pre  = s_prefix;
    const int excl = incl - v + pre;
    if (i < Mc) { g_rowptr[i] = excl; g_cursor[i] = excl; }
    if (b == NSCANB - 1 && t == 255) g_rowptr[Mc] = pre + agg;
}

__global__ void k_scatter(const int* __restrict__ rows,
                          const int* __restrict__ cols,
                          const float* __restrict__ vals, int E) {
    for (int e = blockIdx.x * blockDim.x + threadIdx.x; e < E;
         e += gridDim.x * blockDim.x) {
        int r    = rows[e];
        int slot = atomicAdd(&g_cursor[r], 1);
        g_col[slot] = cols[e];
        g_val[slot] = vals[e];
    }
}

// ---------------- 2. SpMM (templated) ----------------
template<int LIN, int LPREV, int BETA>
__global__ void k_spmm_t(const float* __restrict__ Xin,
                         const float* __restrict__ Xprev,
                         float* __restrict__ Xout, float alpha, float beta) {
    const int r  = blockIdx.x;
    const u32 t  = threadIdx.x;
    const u32 bo = (t >> 5) * (u32)Mc * 32u + (t & 31);
    const int p0 = g_rowptr[r];
    const int p1 = g_rowptr[r + 1];
    const float4* __restrict__ Xi = reinterpret_cast<const float4*>(Xin);

    float4 acc = make_float4(0.f, 0.f, 0.f, 0.f);
    int p = p0;
    for (; p + 7 < p1; p += 8) {
        float4 xv[8];
        float  vv[8];
        #pragma unroll
        for (int j = 0; j < 8; ++j) {
            u32 c = (u32)g_col[p + j];
            vv[j] = g_val[p + j];
            u32 i = LIN ? (c * 128u + t) : (c * 32u + bo);
            xv[j] = Xi[i];
        }
        #pragma unroll
        for (int j = 0; j < 8; ++j) {
            acc.x = fmaf(vv[j], xv[j].x, acc.x);
            acc.y = fmaf(vv[j], xv[j].y, acc.y);
            acc.z = fmaf(vv[j], xv[j].z, acc.z);
            acc.w = fmaf(vv[j], xv[j].w, acc.w);
        }
    }
    if (p + 3 < p1) {
        float4 xv[4];
        float  vv[4];
        #pragma unroll
        for (int j = 0; j < 4; ++j) {
            u32 c = (u32)g_col[p + j];
            vv[j] = g_val[p + j];
            u32 i = LIN ? (c * 128u + t) : (c * 32u + bo);
            xv[j] = Xi[i];
        }
        #pragma unroll
        for (int j = 0; j < 4; ++j) {
            acc.x = fmaf(vv[j], xv[j].x, acc.x);
            acc.y = fmaf(vv[j], xv[j].y, acc.y);
            acc.z = fmaf(vv[j], xv[j].z, acc.z);
            acc.w = fmaf(vv[j], xv[j].w, acc.w);
        }
        p += 4;
    }
    for (; p < p1; ++p) {
        u32 c = (u32)g_col[p];
        float v0 = g_val[p];
        u32 i = LIN ? (c * 128u + t) : (c * 32u + bo);
        float4 xa = Xi[i];
        acc.x = fmaf(v0, xa.x, acc.x);
        acc.y = fmaf(v0, xa.y, acc.y);
        acc.z = fmaf(v0, xa.z, acc.z);
        acc.w = fmaf(v0, xa.w, acc.w);
    }

    float4 o;
    if (BETA) {
        u32 ip = LPREV ? ((u32)r * 128u + t) : ((u32)r * 32u + bo);
        float4 pv = reinterpret_cast<const float4*>(Xprev)[ip];
        o.x = fmaf(alpha, acc.x, beta * pv.x);
        o.y = fmaf(alpha, acc.y, beta * pv.y);
        o.z = fmaf(alpha, acc.z, beta * pv.z);
        o.w = fmaf(alpha, acc.w, beta * pv.w);
    } else {
        o.x = alpha * acc.x; o.y = alpha * acc.y;
        o.z = alpha * acc.z; o.w = alpha * acc.w;
    }
    reinterpret_cast<float4*>(Xout)[(u32)r * 128u + t] = o;
}

// ---------------- 3. wmma fp16 GEMM, cp.async double-buffered ----------------
// CTA tile 128(M) x 128(N); K=512 in 16 stages of 32.
// A single fp16, B = fp16 hi + lo (2-term). D = A*B1 + A*B2, fp32 accumulate.
#define RAWLD 36      // raw A row stride (floats): 144 B
#define ALD 40        // converted A ldm (halves)
#define BLD 136       // B ldm (halves): 272 B rows
// dynamic smem layout (bytes)
#define OFF_RAWA 0                         // [2][128][RAWLD] f32 : 2*18432
#define OFF_B    36864                     // [2][Bh 32x136 | Bl 32x136] : 2*17408
#define OFF_AH   (36864 + 34816)           // [128][ALD] fp16 : 10240
#define GSMEM    (OFF_AH + 10240)          // 81920 B

__global__ __launch_bounds__(256)
void k_gemm_wmma(const float* __restrict__ x, float* __restrict__ Y) {
    extern __shared__ char dsm[];
    float* rawA = reinterpret_cast<float*>(dsm + OFF_RAWA);
    __half* Ah = reinterpret_cast<__half*>(dsm + OFF_AH);
    __shared__ int2  rowB[128];
    __shared__ float stg[8][16][16];

    const int t   = threadIdx.x;
    const int wid = t >> 5, lid = t & 31;
    const int wm  = wid & 3;
    const int wn  = wid >> 2;
    const int r0  = blockIdx.x * 128;
    const bool full = (r0 + 128 <= TOTROWS);
    const u32 sbase = smem_u32p(dsm);

    if (t < 128) {
        int gr = r0 + t;
        int2 rb = make_int2(-1, -1);
        if (gr < TOTROWS) {
            int b = gr / Mc; int m = gr - b * Mc;
            rb.x = (b * Mc + m) * 128;   // x native [b][m][f]
            rb.y = m * 512 + b * 128;    // g_X [m][b][f]
        }
        rowB[t] = rb;
    }
    __syncthreads();

    wmma::fragment<wmma::accumulator, 16, 16, 16, float> acc[2][4];
    #pragma unroll
    for (int mi = 0; mi < 2; ++mi)
        #pragma unroll
        for (int ni = 0; ni < 4; ++ni)
            wmma::fill_fragment(acc[mi][ni], 0.0f);

    // issue cp.async for stage c into buffer c&1
    auto issue = [&](int c) {
        const int buf = c & 1;
        const int kcheb = c >> 2;
        const int f0 = (c & 3) << 5;
        const float* Asrc = (kcheb == 0) ? x : g_X[kcheb];
        const u32 adst0 = sbase + OFF_RAWA + buf * 18432;
        #pragma unroll
        for (int q = 0; q < 4; ++q) {
            int idx = t + (q << 8);
            int row = idx >> 3, seg = idx & 7;
            int2 rb = rowB[row];
            int base = (kcheb == 0) ? rb.x : rb.y;
            if (rb.x < 0) base = 0;   // tail rows: valid dummy src, result discarded
            const float* src = Asrc + base + f0 + (seg << 2);
            CPA16(adst0 + row * 144 + (seg << 4), src);
        }
        const u32 bdst0 = sbase + OFF_B + buf * 17408;
        #pragma unroll
        for (int q = 0; q < 4; ++q) {
            int idx = t + (q << 8);
            int arr = idx >> 9;          // 0 = hi, 1 = lo
            int rix = (idx >> 4) & 31;
            int seg = idx & 15;
            const __half* src =
                (arr ? g_Wl : g_Wh) + ((c << 5) + rix) * 128 + (seg << 3);
            CPA16(bdst0 + arr * 8704 + rix * 272 + (seg << 4), src);
        }
    };

    issue(0);
    CPCOMMIT();

    for (int c = 0; c < 16; ++c) {
        const int buf = c & 1;
        if (c < 15) { issue(c + 1); CPCOMMIT(); CPWAIT1(); }
        else        { CPWAIT0(); }
        __syncthreads();

        // convert rawA[buf] (128x32 f32) -> Ah (fp16)
        const float* ra = rawA + buf * 4608;
        #pragma unroll
        for (int q = 0; q < 4; ++q) {
            int idx = t + (q << 8);
            int row = idx >> 3, c0 = (idx & 7) << 2;
            float4 v = *reinterpret_cast<const float4*>(ra + row * RAWLD + c0);
            __half2 h01 = __floats2half2_rn(v.x, v.y);
            __half2 h23 = __floats2half2_rn(v.z, v.w);
            uint2 u;
            u.x = *reinterpret_cast<u32*>(&h01);
            u.y = *reinterpret_cast<u32*>(&h23);
            *reinterpret_cast<uint2*>(Ah + row * ALD + c0) = u;
        }
        __syncthreads();

        const __half* Bh = reinterpret_cast<const __half*>(dsm + OFF_B + buf * 17408);
        const __half* Bl = Bh + 4352;   // 8704 B / 2

        #pragma unroll
        for (int kk = 0; kk < 2; ++kk) {
            wmma::fragment<wmma::matrix_a, 16, 16, 16, __half, wmma::row_major> ah[2];
            #pragma unroll
            for (int mi = 0; mi < 2; ++mi)
                wmma::load_matrix_sync(ah[mi], Ah + (wm * 32 + mi * 16) * ALD + kk * 16, ALD);
            #pragma unroll
            for (int ni = 0; ni < 4; ++ni) {
                wmma::fragment<wmma::matrix_b, 16, 16, 16, __half, wmma::row_major> bh, bl;
                wmma::load_matrix_sync(bh, Bh + (kk * 16) * BLD + wn * 64 + ni * 16, BLD);
                wmma::load_matrix_sync(bl, Bl + (kk * 16) * BLD + wn * 64 + ni * 16, BLD);
                #pragma unroll
                for (int mi = 0; mi < 2; ++mi) {
                    wmma::mma_sync(acc[mi][ni], ah[mi], bh, acc[mi][ni]);
                    wmma::mma_sync(acc[mi][ni], ah[mi], bl, acc[mi][ni]);
                }
            }
        }
        __syncthreads();
    }

    // epilogue: ReLU + store
    #pragma unroll
    for (int mi = 0; mi < 2; ++mi)
        #pragma unroll
        for (int ni = 0; ni < 4; ++ni)
            #pragma unroll
            for (int e = 0; e < acc[mi][ni].num_elements; ++e)
                acc[mi][ni].x[e] = fmaxf(acc[mi][ni].x[e], 0.0f);

    if (full) {
        #pragma unroll
        for (int mi = 0; mi < 2; ++mi)
            #pragma unroll
            for (int ni = 0; ni < 4; ++ni) {
                int gr = r0 + wm * 32 + mi * 16;
                int gc = wn * 64 + ni * 16;
                wmma::store_matrix_sync(Y + (size_t)gr * 128 + gc,
                                        acc[mi][ni], 128, wmma::mem_row_major);
            }
    } else {
        for (int mi = 0; mi < 2; ++mi)
            for (int ni = 0; ni < 4; ++ni) {
                wmma::store_matrix_sync(&stg[wid][0][0], acc[mi][ni], 16,
                                        wmma::mem_row_major);
                __syncwarp();
                int gc = wn * 64 + ni * 16;
                #pragma unroll
                for (int e = lid; e < 256; e += 32) {
                    int rr = e >> 4, cc = e & 15;
                    int gr = r0 + wm * 32 + mi * 16 + rr;
                    if (gr < TOTROWS)
                        Y[(size_t)gr * 128 + gc + cc] = stg[wid][rr][cc];
                }
                __syncwarp();
            }
    }
}

// ---------------- 4. column sums for mean ----------------
__global__ void k_mean(const float* __restrict__ Y) {
    const int b = blockIdx.y;
    const int t = threadIdx.x;
    const int m0 = blockIdx.x * 128;
    const int m1 = min(m0 + 128, Mc);
    float acc = 0.0f;
    for (int m = m0; m < m1; ++m)
        acc += Y[((size_t)b * Mc + m) * 128 + t];
    atomicAdd(&g_ssum[b * 128 + t], acc);
}

// ---------------- 5. SE block ----------------
__global__ void k_se(const float* __restrict__ Wd, const float* __restrict__ bd,
                     const float* __restrict__ Wu, const float* __restrict__ bu) {
    __shared__ float s[Bc][128];
    __shared__ float d[Bc][16];
    const int t = threadIdx.x;
    #pragma unroll
    for (int b = 0; b < Bc; ++b)
        s[b][t] = g_ssum[b * 128 + t] * (1.0f / (float)Mc);
    __syncthreads();
    if (t < 64) {
        int b = t >> 4, j = t & 15;
        float z = bd[j];
        for (int f = 0; f < 128; ++f) z = fmaf(s[b][f], Wd[f * 16 + j], z);
        d[b][j] = z / (1.0f + expf(-z));
    }
    __syncthreads();
    #pragma unroll
    for (int b = 0; b < Bc; ++b) {
        float z = bu[t];
        for (int j = 0; j < 16; ++j) z = fmaf(d[b][j], Wu[j * 128 + t], z);
        g_u[b * 128 + t] = 1.0f / (1.0f + expf(-z));
    }
}

// ---------------- 6. gated scale ----------------
__global__ void k_scale(float* __restrict__ Y) {
    float4* Y4 = reinterpret_cast<float4*>(Y);
    const int N4 = Bc * Mc * 32;
    for (int i = blockIdx.x * blockDim.x + threadIdx.x; i < N4;
         i += gridDim.x * blockDim.x) {
        int o4 = i & 31;
        int b  = i / (Mc * 32);
        float4 u = reinterpret_cast<const float4*>(g_u)[b * 32 + o4];
        float4 v = Y4[i];
        v.x *= u.x; v.y *= u.y; v.z *= u.z; v.w *= u.w;
        Y4[i] = v;
    }
}

// ---------------- launch ----------------
extern "C" void kernel_launch(void* const* d_in, const int* in_sizes, int n_in,
                              void* d_out, int out_size) {
    const float* x      = (const float*)d_in[0];
    const float* L_vals = (const float*)d_in[1];
    const int*   L_rows = (const int*)  d_in[2];
    const int*   L_cols = (const int*)  d_in[3];
    const float* kern   = (const float*)d_in[4];
    const float* Wd     = (const float*)d_in[5];
    const float* bd     = (const float*)d_in[6];
    const float* Wu     = (const float*)d_in[7];
    const float* bu     = (const float*)d_in[8];
    float* Y = (float*)d_out;
    const int E = in_sizes[1];

    float* X1 = nullptr; cudaGetSymbolAddress((void**)&X1, g_X);
    float* Xs1 = X1 + (size_t)1 * Mc * Dc;
    float* Xs2 = X1 + (size_t)2 * Mc * Dc;
    float* Xs3 = X1 + (size_t)3 * Mc * Dc;
    int*   curp = nullptr; cudaGetSymbolAddress((void**)&curp, g_cursor);
    float* ssump = nullptr; cudaGetSymbolAddress((void**)&ssump, g_ssum);

    static int smem_set = 0;
    if (!smem_set) {
        cudaFuncSetAttribute(k_gemm_wmma,
                             cudaFuncAttributeMaxDynamicSharedMemorySize, GSMEM);
        smem_set = 1;
    }

    cudaMemsetAsync(curp, 0, Mc * sizeof(int));                       // node 0
    cudaMemsetAsync(ssump, 0, Bc * FOUTc * sizeof(float));            // node 1

    k_count  <<<(E + 255) / 256, 256>>>(L_rows, E, kern);             // 2
    k_scan_dl<<<NSCANB, 256>>>();                                     // 3
    k_scatter<<<(E + 255) / 256, 256>>>(L_rows, L_cols, L_vals, E);   // 4

    k_spmm_t<0,0,0><<<Mc, 128>>>(x,   nullptr, Xs1, 1.0f,  0.0f);     // 5 <- ncu -s 5
    k_spmm_t<1,0,1><<<Mc, 128>>>(Xs1, x,       Xs2, 2.0f, -1.0f);     // 6
    k_spmm_t<1,1,1><<<Mc, 128>>>(Xs2, Xs1,     Xs3, 2.0f, -1.0f);     // 7

    k_gemm_wmma<<<(TOTROWS + 127) / 128, 256, GSMEM>>>(x, Y);         // 8
    k_mean  <<<dim3((Mc + 127) / 128, Bc), 128>>>(Y);                 // 9
    k_se    <<<1, 128>>>(Wd, bd, Wu, bu);                             // 10
    k_scale <<<2048, 256>>>(Y);                                       // 11
}

// round 17
// speedup vs baseline: 1.3592x; 1.0545x over previous
#include <cuda_runtime.h>
#include <cuda_fp16.h>
#include <mma.h>
#include <cstdint>
#include <math.h>

using namespace nvcuda;
using u32 = unsigned int;
using u64 = unsigned long long;

// ---------------- problem constants ----------------
#define Bc     4
#define Mc     50000
#define FINc   128
#define FOUTc  128
#define Kc     4
#define Ecap   800000
#define Dc     512
#define TOTROWS (Bc*Mc)
#define NSCANB 196            // ceil(Mc/256)

// ---------------- device scratch ----------------
__device__ float g_X[Kc][Mc * Dc];          // Chebyshev stack [m][b][f]; slot 0 unused
__device__ __half g_Wh[512 * 128];          // W [k][n], fp16
__device__ int   g_rowptr[Mc + 1];
__device__ int   g_cursor[Mc];
__device__ u64   g_scanstate[256];
__device__ int   g_col[Ecap];
__device__ float g_val[Ecap];
__device__ float g_ssum[Bc * FOUTc];
__device__ float g_u[Bc * FOUTc];

// ---------------- cp.async helpers ----------------
__device__ __forceinline__ u32 smem_u32p(const void* p) {
    u32 a;
    asm("{ .reg .u64 t; cvta.to.shared.u64 t, %1; cvt.u32.u64 %0, t; }" : "=r"(a) : "l"(p));
    return a;
}
#define CPA16(dst, src) asm volatile("cp.async.cg.shared.global [%0], [%1], 16;" :: "r"(dst), "l"(src))
#define CPCOMMIT()      asm volatile("cp.async.commit_group;" ::: "memory")
#define CPWAIT1()       asm volatile("cp.async.wait_group 1;" ::: "memory")
#define CPWAIT0()       asm volatile("cp.async.wait_group 0;" ::: "memory")

// ---------------- 1. CSR build (+ fused weight convert) ----------------
__global__ void k_count(const int* __restrict__ rows, int E,
                        const float* __restrict__ kern) {
    int gid = blockIdx.x * blockDim.x + threadIdx.x;
    int stride = gridDim.x * blockDim.x;
    if (gid < 256) g_scanstate[gid] = 0ULL;
    for (int i = gid; i < 512 * 128; i += stride) {
        int k = i >> 7, n = i & 127;
        int kc = k >> 7, f = k & 127;
        g_Wh[i] = __float2half_rn(kern[(f * 4 + kc) * 128 + n]);
    }
    for (int e = gid; e < E; e += stride)
        atomicAdd(&g_cursor[rows[e]], 1);
}

// single-kernel decoupled-lookback scan
__global__ void k_scan_dl() {
    __shared__ int s[256];
    __shared__ int s_prefix;
    const int b = blockIdx.x, t = threadIdx.x;
    const int i = b * 256 + t;
    int v = (i < Mc) ? g_cursor[i] : 0;
    s[t] = v;
    __syncthreads();
    #pragma unroll
    for (int off = 1; off < 256; off <<= 1) {
        int a = (t >= off) ? s[t - off] : 0;
        __syncthreads();
        s[t] += a;
        __syncthreads();
    }
    const int incl = s[t];
    const int agg  = s[255];

    if (t == 0) {
        u64 st = (b == 0) ? ((2ULL << 32) | (u32)agg) : ((1ULL << 32) | (u32)agg);
        atomicExch(&g_scanstate[b], st);
        if (b == 0) s_prefix = 0;
    }

    if (b > 0 && t < 32) {
        int running = 0;
        int idx = b - 1;
        while (true) {
            int j = idx - t;
            u64 st = 0;
            if (j >= 0) {
                do { st = atomicAdd(&g_scanstate[j], 0ULL); } while ((st >> 32) == 0);
            }
            int flag = (j >= 0) ? (int)(st >> 32) : 0;
            int val  = (int)(st & 0xffffffffULL);
            u32 pmask = __ballot_sync(0xffffffffu, flag == 2);
            if (pmask) {
                int lead = __ffs(pmask) - 1;
                int contrib = (t <= lead) ? val : 0;
                #pragma unroll
                for (int o = 16; o; o >>= 1) contrib += __shfl_down_sync(0xffffffffu, contrib, o);
                if (t == 0) s_prefix = running + contrib;
                break;
            } else {
                int contrib = (j >= 0) ? val : 0;
                #pragma unroll
                for (int o = 16; o; o >>= 1) contrib += __shfl_down_sync(0xffffffffu, contrib, o);
                running += __shfl_sync(0xffffffffu, contrib, 0);
                idx -= 32;
            }
        }
        if (t == 0)
            atomicExch(&g_scanstate[b], (2ULL << 32) | (u32)(s_prefix + agg));
    }
    __syncthreads();
    const int pre  = s_prefix;
    const int excl = incl - v + pre;
    if (i < Mc) { g_rowptr[i] = excl; g_cursor[i] = excl; }
    if (b == NSCANB - 1 && t == 255) g_rowptr[Mc] = pre + agg;
}

__global__ void k_scatter(const int* __restrict__ rows,
                          const int* __restrict__ cols,
                          const float* __restrict__ vals, int E) {
    for (int e = blockIdx.x * blockDim.x + threadIdx.x; e < E;
         e += gridDim.x * blockDim.x) {
        int r    = rows[e];
        int slot = atomicAdd(&g_cursor[r], 1);
        g_col[slot] = cols[e];
        g_val[slot] = vals[e];
    }
}

// ---------------- 2. SpMM (templated) ----------------
template<int LIN, int LPREV, int BETA>
__global__ void k_spmm_t(const float* __restrict__ Xin,
                         const float* __restrict__ Xprev,
                         float* __restrict__ Xout, float alpha, float beta) {
    const int r  = blockIdx.x;
    const u32 t  = threadIdx.x;
    const u32 bo = (t >> 5) * (u32)Mc * 32u + (t & 31);
    const int p0 = g_rowptr[r];
    const int p1 = g_rowptr[r + 1];
    const float4* __restrict__ Xi = reinterpret_cast<const float4*>(Xin);

    float4 acc = make_float4(0.f, 0.f, 0.f, 0.f);
    int p = p0;
    for (; p + 7 < p1; p += 8) {
        float4 xv[8];
        float  vv[8];
        #pragma unroll
        for (int j = 0; j < 8; ++j) {
            u32 c = (u32)g_col[p + j];
            vv[j] = g_val[p + j];
            u32 i = LIN ? (c * 128u + t) : (c * 32u + bo);
            xv[j] = Xi[i];
        }
        #pragma unroll
        for (int j = 0; j < 8; ++j) {
            acc.x = fmaf(vv[j], xv[j].x, acc.x);
            acc.y = fmaf(vv[j], xv[j].y, acc.y);
            acc.z = fmaf(vv[j], xv[j].z, acc.z);
            acc.w = fmaf(vv[j], xv[j].w, acc.w);
        }
    }
    if (p + 3 < p1) {
        float4 xv[4];
        float  vv[4];
        #pragma unroll
        for (int j = 0; j < 4; ++j) {
            u32 c = (u32)g_col[p + j];
            vv[j] = g_val[p + j];
            u32 i = LIN ? (c * 128u + t) : (c * 32u + bo);
            xv[j] = Xi[i];
        }
        #pragma unroll
        for (int j = 0; j < 4; ++j) {
            acc.x = fmaf(vv[j], xv[j].x, acc.x);
            acc.y = fmaf(vv[j], xv[j].y, acc.y);
            acc.z = fmaf(vv[j], xv[j].z, acc.z);
            acc.w = fmaf(vv[j], xv[j].w, acc.w);
        }
        p += 4;
    }
    for (; p < p1; ++p) {
        u32 c = (u32)g_col[p];
        float v0 = g_val[p];
        u32 i = LIN ? (c * 128u + t) : (c * 32u + bo);
        float4 xa = Xi[i];
        acc.x = fmaf(v0, xa.x, acc.x);
        acc.y = fmaf(v0, xa.y, acc.y);
        acc.z = fmaf(v0, xa.z, acc.z);
        acc.w = fmaf(v0, xa.w, acc.w);
    }

    float4 o;
    if (BETA) {
        u32 ip = LPREV ? ((u32)r * 128u + t) : ((u32)r * 32u + bo);
        float4 pv = reinterpret_cast<const float4*>(Xprev)[ip];
        o.x = fmaf(alpha, acc.x, beta * pv.x);
        o.y = fmaf(alpha, acc.y, beta * pv.y);
        o.z = fmaf(alpha, acc.z, beta * pv.z);
        o.w = fmaf(alpha, acc.w, beta * pv.w);
    } else {
        o.x = alpha * acc.x; o.y = alpha * acc.y;
        o.z = alpha * acc.z; o.w = alpha * acc.w;
    }
    reinterpret_cast<float4*>(Xout)[(u32)r * 128u + t] = o;
}

// ---------------- 3. wmma fp16 GEMM (single-term), cp.async double-buffered ----
// CTA tile 128(M) x 128(N); K=512 in 16 stages of 32.
// A fp16, B fp16: D = A*B, fp32 accumulate. 1 MMA/k-step.
#define RAWLD 36      // raw A row stride (floats): 144 B
#define ALD 40        // converted A ldm (halves)
#define BLD 136       // B ldm (halves): 272 B rows
// dynamic smem layout (bytes)
#define OFF_RAWA 0                         // [2][128][RAWLD] f32 : 2*18432
#define OFF_B    36864                     // [2][32x136 fp16]   : 2*8704
#define OFF_AH   (36864 + 17408)           // [128][ALD] fp16 : 10240
#define GSMEM    (OFF_AH + 10240)          // 64512 B

__global__ __launch_bounds__(256)
void k_gemm_wmma(const float* __restrict__ x, float* __restrict__ Y) {
    extern __shared__ char dsm[];
    float* rawA = reinterpret_cast<float*>(dsm + OFF_RAWA);
    __half* Ah = reinterpret_cast<__half*>(dsm + OFF_AH);
    __shared__ int2  rowB[128];
    __shared__ float stg[8][16][16];

    const int t   = threadIdx.x;
    const int wid = t >> 5, lid = t & 31;
    const int wm  = wid & 3;
    const int wn  = wid >> 2;
    const int r0  = blockIdx.x * 128;
    const bool full = (r0 + 128 <= TOTROWS);
    const u32 sbase = smem_u32p(dsm);

    if (t < 128) {
        int gr = r0 + t;
        int2 rb = make_int2(-1, -1);
        if (gr < TOTROWS) {
            int b = gr / Mc; int m = gr - b * Mc;
            rb.x = (b * Mc + m) * 128;   // x native [b][m][f]
            rb.y = m * 512 + b * 128;    // g_X [m][b][f]
        }
        rowB[t] = rb;
    }
    __syncthreads();

    wmma::fragment<wmma::accumulator, 16, 16, 16, float> acc[2][4];
    #pragma unroll
    for (int mi = 0; mi < 2; ++mi)
        #pragma unroll
        for (int ni = 0; ni < 4; ++ni)
            wmma::fill_fragment(acc[mi][ni], 0.0f);

    // issue cp.async for stage c into buffer c&1
    auto issue = [&](int c) {
        const int buf = c & 1;
        const int kcheb = c >> 2;
        const int f0 = (c & 3) << 5;
        const float* Asrc = (kcheb == 0) ? x : g_X[kcheb];
        const u32 adst0 = sbase + OFF_RAWA + buf * 18432;
        #pragma unroll
        for (int q = 0; q < 4; ++q) {
            int idx = t + (q << 8);
            int row = idx >> 3, seg = idx & 7;
            int2 rb = rowB[row];
            int base = (kcheb == 0) ? rb.x : rb.y;
            if (rb.x < 0) base = 0;   // tail rows: valid dummy src, result discarded
            const float* src = Asrc + base + f0 + (seg << 2);
            CPA16(adst0 + row * 144 + (seg << 4), src);
        }
        const u32 bdst0 = sbase + OFF_B + buf * 8704;
        #pragma unroll
        for (int q = 0; q < 2; ++q) {
            int idx = t + (q << 8);
            int rix = idx >> 4;          // 0..31
            int seg = idx & 15;
            const __half* src = g_Wh + ((c << 5) + rix) * 128 + (seg << 3);
            CPA16(bdst0 + rix * 272 + (seg << 4), src);
        }
    };

    issue(0);
    CPCOMMIT();

    for (int c = 0; c < 16; ++c) {
        const int buf = c & 1;
        if (c < 15) { issue(c + 1); CPCOMMIT(); CPWAIT1(); }
        else        { CPWAIT0(); }
        __syncthreads();

        // convert rawA[buf] (128x32 f32) -> Ah (fp16)
        const float* ra = rawA + buf * 4608;
        #pragma unroll
        for (int q = 0; q < 4; ++q) {
            int idx = t + (q << 8);
            int row = idx >> 3, c0 = (idx & 7) << 2;
            float4 v = *reinterpret_cast<const float4*>(ra + row * RAWLD + c0);
            __half2 h01 = __floats2half2_rn(v.x, v.y);
            __half2 h23 = __floats2half2_rn(v.z, v.w);
            uint2 u;
            u.x = *reinterpret_cast<u32*>(&h01);
            u.y = *reinterpret_cast<u32*>(&h23);
            *reinterpret_cast<uint2*>(Ah + row * ALD + c0) = u;
        }
        __syncthreads();

        const __half* Bh = reinterpret_cast<const __half*>(dsm + OFF_B + buf * 8704);

        #pragma unroll
        for (int kk = 0; kk < 2; ++kk) {
            wmma::fragment<wmma::matrix_a, 16, 16, 16, __half, wmma::row_major> ah[2];
            #pragma unroll
            for (int mi = 0; mi < 2; ++mi)
                wmma::load_matrix_sync(ah[mi], Ah + (wm * 32 + mi * 16) * ALD + kk * 16, ALD);
            #pragma unroll
            for (int ni = 0; ni < 4; ++ni) {
                wmma::fragment<wmma::matrix_b, 16, 16, 16, __half, wmma::row_major> bh;
                wmma::load_matrix_sync(bh, Bh + (kk * 16) * BLD + wn * 64 + ni * 16, BLD);
                #pragma unroll
                for (int mi = 0; mi < 2; ++mi)
                    wmma::mma_sync(acc[mi][ni], ah[mi], bh, acc[mi][ni]);
            }
        }
        __syncthreads();
    }

    // epilogue: ReLU + store
    #pragma unroll
    for (int mi = 0; mi < 2; ++mi)
        #pragma unroll
        for (int ni = 0; ni < 4; ++ni)
            #pragma unroll
            for (int e = 0; e < acc[mi][ni].num_elements; ++e)
                acc[mi][ni].x[e] = fmaxf(acc[mi][ni].x[e], 0.0f);

    if (full) {
        #pragma unroll
        for (int mi = 0; mi < 2; ++mi)
            #pragma unroll
            for (int ni = 0; ni < 4; ++ni) {
                int gr = r0 + wm * 32 + mi * 16;
                int gc = wn * 64 + ni * 16;
                wmma::store_matrix_sync(Y + (size_t)gr * 128 + gc,
                                        acc[mi][ni], 128, wmma::mem_row_major);
            }
    } else {
        for (int mi = 0; mi < 2; ++mi)
            for (int ni = 0; ni < 4; ++ni) {
                wmma::store_matrix_sync(&stg[wid][0][0], acc[mi][ni], 16,
                                        wmma::mem_row_major);
                __syncwarp();
                int gc = wn * 64 + ni * 16;
                #pragma unroll
                for (int e = lid; e < 256; e += 32) {
                    int rr = e >> 4, cc = e & 15;
                    int gr = r0 + wm * 32 + mi * 16 + rr;
                    if (gr < TOTROWS)
                        Y[(size_t)gr * 128 + gc + cc] = stg[wid][rr][cc];
                }
                __syncwarp();
            }
    }
}

// ---------------- 4. column sums for mean ----------------
__global__ void k_mean(const float* __restrict__ Y) {
    const int b = blockIdx.y;
    const int t = threadIdx.x;
    const int m0 = blockIdx.x * 128;
    const int m1 = min(m0 + 128, Mc);
    float acc = 0.0f;
    for (int m = m0; m < m1; ++m)
        acc += Y[((size_t)b * Mc + m) * 128 + t];
    atomicAdd(&g_ssum[b * 128 + t], acc);
}

// ---------------- 5. SE block ----------------
__global__ void k_se(const float* __restrict__ Wd, const float* __restrict__ bd,
                     const float* __restrict__ Wu, const float* __restrict__ bu) {
    __shared__ float s[Bc][128];
    __shared__ float d[Bc][16];
    const int t = threadIdx.x;
    #pragma unroll
    for (int b = 0; b < Bc; ++b)
        s[b][t] = g_ssum[b * 128 + t] * (1.0f / (float)Mc);
    __syncthreads();
    if (t < 64) {
        int b = t >> 4, j = t & 15;
        float z = bd[j];
        for (int f = 0; f < 128; ++f) z = fmaf(s[b][f], Wd[f * 16 + j], z);
        d[b][j] = z / (1.0f + expf(-z));
    }
    __syncthreads();
    #pragma unroll
    for (int b = 0; b < Bc; ++b) {
        float z = bu[t];
        for (int j = 0; j < 16; ++j) z = fmaf(d[b][j], Wu[j * 128 + t], z);
        g_u[b * 128 + t] = 1.0f / (1.0f + expf(-z));
    }
}

// ---------------- 6. gated scale ----------------
__global__ void k_scale(float* __restrict__ Y) {
    float4* Y4 = reinterpret_cast<float4*>(Y);
    const int N4 = Bc * Mc * 32;
    for (int i = blockIdx.x * blockDim.x + threadIdx.x; i < N4;
         i += gridDim.x * blockDim.x) {
        int o4 = i & 31;
        int b  = i / (Mc * 32);
        float4 u = reinterpret_cast<const float4*>(g_u)[b * 32 + o4];
        float4 v = Y4[i];
        v.x *= u.x; v.y *= u.y; v.z *= u.z; v.w *= u.w;
        Y4[i] = v;
    }
}

// ---------------- launch ----------------
extern "C" void kernel_launch(void* const* d_in, const int* in_sizes, int n_in,
                              void* d_out, int out_size) {
    const float* x      = (const float*)d_in[0];
    const float* L_vals = (const float*)d_in[1];
    const int*   L_rows = (const int*)  d_in[2];
    const int*   L_cols = (const int*)  d_in[3];
    const float* kern   = (const float*)d_in[4];
    const float* Wd     = (const float*)d_in[5];
    const float* bd     = (const float*)d_in[6];
    const float* Wu     = (const float*)d_in[7];
    const float* bu     = (const float*)d_in[8];
    float* Y = (float*)d_out;
    const int E = in_sizes[1];

    float* X1 = nullptr; cudaGetSymbolAddress((void**)&X1, g_X);
    float* Xs1 = X1 + (size_t)1 * Mc * Dc;
    float* Xs2 = X1 + (size_t)2 * Mc * Dc;
    float* Xs3 = X1 + (size_t)3 * Mc * Dc;
    int*   curp = nullptr; cudaGetSymbolAddress((void**)&curp, g_cursor);
    float* ssump = nullptr; cudaGetSymbolAddress((void**)&ssump, g_ssum);

    static int smem_set = 0;
    if (!smem_set) {
        cudaFuncSetAttribute(k_gemm_wmma,
                             cudaFuncAttributeMaxDynamicSharedMemorySize, GSMEM);
        smem_set = 1;
    }

    cudaMemsetAsync(curp, 0, Mc * sizeof(int));                       // node 0
    cudaMemsetAsync(ssump, 0, Bc * FOUTc * sizeof(float));            // node 1

    k_count  <<<(E + 255) / 256, 256>>>(L_rows, E, kern);             // 2
    k_scan_dl<<<NSCANB, 256>>>();                                     // 3
    k_scatter<<<(E + 255) / 256, 256>>>(L_rows, L_cols, L_vals, E);   // 4

    k_spmm_t<0,0,0><<<Mc, 128>>>(x,   nullptr, Xs1, 1.0f,  0.0f);     // 5 <- ncu -s 5
    k_spmm_t<1,0,1><<<Mc, 128>>>(Xs1, x,       Xs2, 2.0f, -1.0f);     // 6
    k_spmm_t<1,1,1><<<Mc, 128>>>(Xs2, Xs1,     Xs3, 2.0f, -1.0f);     // 7

    k_gemm_wmma<<<(TOTROWS + 127) / 128, 256, GSMEM>>>(x, Y);         // 8
    k_mean  <<<dim3((Mc + 127) / 128, Bc), 128>>>(Y);                 // 9
    k_se    <<<1, 128>>>(Wd, bd, Wu, bu);                             // 10
    k_scale <<<2048, 256>>>(Y);                                       // 11
}